// round 8
// baseline (speedup 1.0000x reference)
#include <cuda_runtime.h>
#include <stdint.h>

// ---------------------------------------------------------------------------
// ExtractGraph: maxpool2x2 -> +uniform noise -> diagonal-stencil adjacency
// (transposed) -> bernoulli(0.5) dropout. Output float32.
// RNG = JAX threefry2x32, partitionable scheme:
//   split(key)[i]      = both output words of threefry(key, (0, i))
//   random_bits(32)[t] = o0 ^ o1 of threefry(key, (hi(t), lo(t)))
// Cipher load-balance: pool (mem-bound) runs noise cipher + dropout cipher
// for rows [0,1024) (bitmask stash); graph runs dropout cipher for rows
// [1024,2048) only. Equalizes max(alu, mem) across the two kernels.
// ---------------------------------------------------------------------------

#define PM 2048
#define PN 2048

static __device__ float    g_dnT[(size_t)PM * PN];       // d_noised TRANSPOSED
static __device__ unsigned g_keep[(size_t)(PM / 2) * (PN / 32)];  // rows [0,1024) keep bits
static __device__ unsigned g_min_u;
static __device__ unsigned g_max_u;

__host__ __device__ __forceinline__ uint32_t rotl32(uint32_t x, int d) {
    return (x << d) | (x >> (32 - d));
}

// Threefry-2x32, 20 rounds, exactly as in jax/_src/prng.py.
__host__ __device__ __forceinline__ void tf2x32(uint32_t k0, uint32_t k1,
                                                uint32_t c0, uint32_t c1,
                                                uint32_t& o0, uint32_t& o1) {
    uint32_t ks2 = k0 ^ k1 ^ 0x1BD11BDAu;
    uint32_t x0 = c0 + k0;
    uint32_t x1 = c1 + k1;
#define TFR(R) { x0 += x1; x1 = rotl32(x1, R); x1 ^= x0; }
    TFR(13) TFR(15) TFR(26) TFR(6)
    x0 += k1;  x1 += ks2 + 1u;
    TFR(17) TFR(29) TFR(16) TFR(24)
    x0 += ks2; x1 += k0 + 2u;
    TFR(13) TFR(15) TFR(26) TFR(6)
    x0 += k0;  x1 += k1 + 3u;
    TFR(17) TFR(29) TFR(16) TFR(24)
    x0 += k1;  x1 += ks2 + 4u;
    TFR(13) TFR(15) TFR(26) TFR(6)
    x0 += ks2; x1 += k0 + 5u;
#undef TFR
    o0 = x0; o1 = x1;
}

__device__ __forceinline__ uint32_t tf_bits32(uint32_t k0, uint32_t k1,
                                              uint32_t c0, uint32_t c1) {
    uint32_t o0, o1;
    tf2x32(k0, k1, c0, c1, o0, o1);
    return o0 ^ o1;
}

// JAX uniform(0,1) float32 from 32 random bits.
__device__ __forceinline__ float u01(uint32_t b) {
    return __uint_as_float((b >> 9) | 0x3f800000u) - 1.0f;
}

// keep (bernoulli p=0.5): u01(b) < 0.5  <=>  top bit of b clear (exact).
__device__ __forceinline__ bool keep_of(uint32_t b) { return (b >> 31) == 0u; }

// Order-preserving float<->uint mapping for atomic min/max (no NaNs in input).
__device__ __forceinline__ unsigned f2sortable(float f) {
    unsigned u = __float_as_uint(f);
    return (u & 0x80000000u) ? ~u : (u | 0x80000000u);
}
__device__ __forceinline__ float sortable2f(unsigned u) {
    unsigned b = (u & 0x80000000u) ? (u ^ 0x80000000u) : ~u;
    return __uint_as_float(b);
}

// Kernel A: maxpool 2x2 + noise cipher (+ dropout cipher for rows < 1024,
// ballot-packed to g_keep), transposed d_noised write, min/max reduction.
__global__ void __launch_bounds__(256) pool_noise_kernel(
    const float* __restrict__ dc,
    uint32_t kn0, uint32_t kn1, uint32_t kd0, uint32_t kd1) {
    __shared__ float s[32][33];
    const int tx = threadIdx.x, ty = threadIdx.y;
    const int j0 = blockIdx.x * 32;      // pool col tile
    const int i0 = blockIdx.y * 32;      // pool row tile
    const int j  = j0 + tx;
    const bool do_drop = (i0 < PM / 2);  // uniform per block

    unsigned lmin = 0xFFFFFFFFu, lmax = 0u;

#pragma unroll
    for (int k = 0; k < 4; ++k) {
        const int i = i0 + ty + 8 * k;
        const float2* row0 = reinterpret_cast<const float2*>(dc + ((uint32_t)(2 * i) << 12));
        const float2* row1 = reinterpret_cast<const float2*>(dc + ((uint32_t)(2 * i + 1) << 12));
        const float2 a = __ldg(&row0[j]);
        const float2 b = __ldg(&row1[j]);
        const float p = fmaxf(fmaxf(a.x, a.y), fmaxf(b.x, b.y));

        const unsigned e = f2sortable(p);
        lmin = min(lmin, e);
        lmax = max(lmax, e);

        const uint32_t t = ((uint32_t)i << 11) + (uint32_t)j;
        const uint32_t bn = tf_bits32(kn0, kn1, 0u, t);
        s[tx][ty + 8 * k] = p + u01(bn);

        if (do_drop) {
            const uint32_t bd = tf_bits32(kd0, kd1, 0u, t);
            const unsigned ballot = __ballot_sync(0xffffffffu, keep_of(bd));
            if (tx == 0) g_keep[((uint32_t)i << 6) + (uint32_t)blockIdx.x] = ballot;
        }
    }
    __syncthreads();

    // transposed, coalesced write: g_dnT[j][i]
#pragma unroll
    for (int k = 0; k < 4; ++k) {
        const int lj = ty + 8 * k;
        g_dnT[((uint32_t)(j0 + lj) << 11) + i0 + tx] = s[lj][tx];
    }

    lmin = __reduce_min_sync(0xffffffffu, lmin);
    lmax = __reduce_max_sync(0xffffffffu, lmax);
    __shared__ unsigned rmin[8], rmax[8];
    if (tx == 0) { rmin[ty] = lmin; rmax[ty] = lmax; }
    __syncthreads();
    if (ty == 0 && tx == 0) {
        unsigned m0 = rmin[0], m1 = rmax[0];
#pragma unroll
        for (int w = 1; w < 8; ++w) { m0 = min(m0, rmin[w]); m1 = max(m1, rmax[w]); }
        atomicMin(&g_min_u, m0);
        atomicMax(&g_max_u, m1);
    }
}

// Kernel B: 4 elements/thread, float4 I/O, simplified mask.
//   (dx=-1,dy=-1): c>=1            && r>=1            nb = dn[r-1][c-1]
//   (dx=-1,dy=+1): c>=1 && c<=2046 && r>=1 && r<=2046 nb = dn[r-1][c+1]
//   (dx=+1,dy=-1): c>=1            && r<=2046         nb = dn[r+1][c-1]
//   (dx=+1,dy=+1): c<=2046         && r<=2046         nb = dn[r+1][c+1]
// Dropout: rows < 1024 read precomputed g_keep; rows >= 1024 compute cipher.
__global__ void __launch_bounds__(256) graph_kernel(
    float* __restrict__ out, uint32_t kd0, uint32_t kd1) {
    const int c0 = (blockIdx.x * 32 + threadIdx.x) * 4;
    const int r  = blockIdx.y * 8 + threadIdx.y;

    const float thr = (sortable2f(g_max_u) - sortable2f(g_min_u)) * (1.0f / 2048.0f);

    const bool rm = (r >= 1), rp = (r <= PM - 2);
    const uint32_t rowb = (uint32_t)r << 11;
    const float4 ctr = *reinterpret_cast<const float4*>(&g_dnT[rowb + c0]);

    const float* up_row = &g_dnT[(uint32_t)(rm ? r - 1 : r) << 11];
    const float* dn_row = &g_dnT[(uint32_t)(rp ? r + 1 : r) << 11];
    const int cl = (c0 > 0) ? c0 - 1 : 0;
    const int cr = (c0 + 4 < PN) ? c0 + 4 : PN - 1;

    float up[6], dw[6];
    {
        const float4 u4 = *reinterpret_cast<const float4*>(up_row + c0);
        const float4 d4 = *reinterpret_cast<const float4*>(dn_row + c0);
        up[1] = u4.x; up[2] = u4.y; up[3] = u4.z; up[4] = u4.w;
        dw[1] = d4.x; dw[2] = d4.y; dw[3] = d4.z; dw[4] = d4.w;
        up[0] = up_row[cl]; up[5] = up_row[cr];
        dw[0] = dn_row[cl]; dw[5] = dn_row[cr];
    }

    // dropout keep bits (uniform branch per warp: r is warp-constant)
    bool keep[4];
    if (r < PM / 2) {
        const unsigned kw = g_keep[((uint32_t)r << 6) + ((uint32_t)c0 >> 5)];
#pragma unroll
        for (int e = 0; e < 4; ++e) keep[e] = (kw >> ((c0 + e) & 31)) & 1u;
    } else {
#pragma unroll
        for (int e = 0; e < 4; ++e)
            keep[e] = keep_of(tf_bits32(kd0, kd1, 0u, rowb + (uint32_t)(c0 + e)));
    }

    const float cx[4] = {ctr.x, ctr.y, ctr.z, ctr.w};
    float res[4];
#pragma unroll
    for (int e = 0; e < 4; ++e) {
        const int c = c0 + e;
        const bool cm = (c >= 1), cp = (c <= PN - 2);
        const float x = cx[e];
        bool adj = false;
        adj |= (cm && rm)             && (fabsf(up[e]     - x) <= thr);
        adj |= (cm && cp && rm && rp) && (fabsf(up[e + 2] - x) <= thr);
        adj |= (cm && rp)             && (fabsf(dw[e]     - x) <= thr);
        adj |= (cp && rp)             && (fabsf(dw[e + 2] - x) <= thr);
        res[e] = (adj && keep[e]) ? 1.0f : 0.0f;
    }

    *reinterpret_cast<float4*>(&out[rowb + c0]) =
        make_float4(res[0], res[1], res[2], res[3]);
}

extern "C" void kernel_launch(void* const* d_in, const int* in_sizes, int n_in,
                              void* d_out, int out_size) {
    (void)in_sizes; (void)n_in; (void)out_size;
    const float* dc = (const float*)d_in[0];
    float* out = (float*)d_out;

    // jax.random.key(1) -> (0,1). Partitionable split:
    uint32_t kn0, kn1, kd0, kd1;
    tf2x32(0u, 1u, 0u, 0u, kn0, kn1);   // k_noise
    tf2x32(0u, 1u, 0u, 1u, kd0, kd1);   // k_drop

    void* pmin = nullptr; void* pmax = nullptr;
    cudaGetSymbolAddress(&pmin, g_min_u);
    cudaGetSymbolAddress(&pmax, g_max_u);
    cudaMemsetAsync(pmin, 0xFF, 4);
    cudaMemsetAsync(pmax, 0x00, 4);

    pool_noise_kernel<<<dim3(64, 64), dim3(32, 8)>>>(dc, kn0, kn1, kd0, kd1);
    graph_kernel<<<dim3(16, 256), dim3(32, 8)>>>(out, kd0, kd1);
}

// round 9
// speedup vs baseline: 1.0988x; 1.0988x over previous
#include <cuda_runtime.h>
#include <stdint.h>

// ---------------------------------------------------------------------------
// ExtractGraph: maxpool2x2 -> +uniform noise -> diagonal-stencil adjacency
// (transposed) -> bernoulli(0.5) dropout. Output float32.
// RNG = JAX threefry2x32, partitionable scheme:
//   split(key)[i]      = both output words of threefry(key, (0, i))
//   random_bits(32)[t] = o0 ^ o1 of threefry(key, (hi(t), lo(t)))
// R9: pool = noise cipher only (R7 proven). graph = dropout cipher + stencil
// with interior/boundary block specialization (rim = 2/4096 blocks per axis).
// ---------------------------------------------------------------------------

#define PM 2048
#define PN 2048

static __device__ float    g_dnT[(size_t)PM * PN];   // d_noised TRANSPOSED: g_dnT[j][i]
static __device__ unsigned g_min_u;
static __device__ unsigned g_max_u;

__host__ __device__ __forceinline__ uint32_t rotl32(uint32_t x, int d) {
    return (x << d) | (x >> (32 - d));
}

// Threefry-2x32, 20 rounds, exactly as in jax/_src/prng.py.
__host__ __device__ __forceinline__ void tf2x32(uint32_t k0, uint32_t k1,
                                                uint32_t c0, uint32_t c1,
                                                uint32_t& o0, uint32_t& o1) {
    uint32_t ks2 = k0 ^ k1 ^ 0x1BD11BDAu;
    uint32_t x0 = c0 + k0;
    uint32_t x1 = c1 + k1;
#define TFR(R) { x0 += x1; x1 = rotl32(x1, R); x1 ^= x0; }
    TFR(13) TFR(15) TFR(26) TFR(6)
    x0 += k1;  x1 += ks2 + 1u;
    TFR(17) TFR(29) TFR(16) TFR(24)
    x0 += ks2; x1 += k0 + 2u;
    TFR(13) TFR(15) TFR(26) TFR(6)
    x0 += k0;  x1 += k1 + 3u;
    TFR(17) TFR(29) TFR(16) TFR(24)
    x0 += k1;  x1 += ks2 + 4u;
    TFR(13) TFR(15) TFR(26) TFR(6)
    x0 += ks2; x1 += k0 + 5u;
#undef TFR
    o0 = x0; o1 = x1;
}

__device__ __forceinline__ uint32_t tf_bits32(uint32_t k0, uint32_t k1,
                                              uint32_t c0, uint32_t c1) {
    uint32_t o0, o1;
    tf2x32(k0, k1, c0, c1, o0, o1);
    return o0 ^ o1;
}

// JAX uniform(0,1) float32 from 32 random bits.
__device__ __forceinline__ float u01(uint32_t b) {
    return __uint_as_float((b >> 9) | 0x3f800000u) - 1.0f;
}

// keep (bernoulli p=0.5): u01(b) < 0.5  <=>  top bit clear (exact).
__device__ __forceinline__ bool keep_of(uint32_t b) { return (b >> 31) == 0u; }

// Order-preserving float<->uint mapping for atomic min/max (no NaNs in input).
__device__ __forceinline__ unsigned f2sortable(float f) {
    unsigned u = __float_as_uint(f);
    return (u & 0x80000000u) ? ~u : (u | 0x80000000u);
}
__device__ __forceinline__ float sortable2f(unsigned u) {
    unsigned b = (u & 0x80000000u) ? (u ^ 0x80000000u) : ~u;
    return __uint_as_float(b);
}

// Kernel A (R7 proven): maxpool 2x2 + threefry noise, transposed write via
// smem tile, min/max block reduction into global atomics.
__global__ void __launch_bounds__(256) pool_noise_kernel(
    const float* __restrict__ dc, uint32_t kn0, uint32_t kn1) {
    __shared__ float s[32][33];
    const int tx = threadIdx.x, ty = threadIdx.y;
    const int j0 = blockIdx.x * 32;
    const int i0 = blockIdx.y * 32;
    const int j  = j0 + tx;

    unsigned lmin = 0xFFFFFFFFu, lmax = 0u;

#pragma unroll
    for (int k = 0; k < 4; ++k) {
        const int i = i0 + ty + 8 * k;
        const float2* row0 = reinterpret_cast<const float2*>(dc + ((uint32_t)(2 * i) << 12));
        const float2* row1 = reinterpret_cast<const float2*>(dc + ((uint32_t)(2 * i + 1) << 12));
        const float2 a = __ldg(&row0[j]);
        const float2 b = __ldg(&row1[j]);
        const float p = fmaxf(fmaxf(a.x, a.y), fmaxf(b.x, b.y));

        const unsigned e = f2sortable(p);
        lmin = min(lmin, e);
        lmax = max(lmax, e);

        const uint32_t bits = tf_bits32(kn0, kn1, 0u, ((uint32_t)i << 11) + j);
        s[tx][ty + 8 * k] = p + u01(bits);
    }
    __syncthreads();

#pragma unroll
    for (int k = 0; k < 4; ++k) {
        const int lj = ty + 8 * k;
        g_dnT[((uint32_t)(j0 + lj) << 11) + i0 + tx] = s[lj][tx];
    }

    lmin = __reduce_min_sync(0xffffffffu, lmin);
    lmax = __reduce_max_sync(0xffffffffu, lmax);
    __shared__ unsigned rmin[8], rmax[8];
    if (tx == 0) { rmin[ty] = lmin; rmax[ty] = lmax; }
    __syncthreads();
    if (ty == 0 && tx == 0) {
        unsigned m0 = rmin[0], m1 = rmax[0];
#pragma unroll
        for (int w = 1; w < 8; ++w) { m0 = min(m0, rmin[w]); m1 = max(m1, rmax[w]); }
        atomicMin(&g_min_u, m0);
        atomicMax(&g_max_u, m1);
    }
}

// Kernel B: 4 elements/thread, float4 I/O. Interior blocks (not on the grid
// rim) take a maskless fmin-reduction path; rim blocks take the general
// (R7-proven) guarded path. Branch is uniform per block.
__global__ void __launch_bounds__(256) graph_kernel(
    float* __restrict__ out, uint32_t kd0, uint32_t kd1) {
    const int c0 = (blockIdx.x * 32 + threadIdx.x) * 4;
    const int r  = blockIdx.y * 8 + threadIdx.y;

    const float thr = (sortable2f(g_max_u) - sortable2f(g_min_u)) * (1.0f / 2048.0f);
    const uint32_t rowb = (uint32_t)r << 11;

    // dropout: 4 independent cipher chains (good ILP); issue first so the
    // ALU work overlaps the stencil loads below.
    bool keep[4];
#pragma unroll
    for (int e = 0; e < 4; ++e)
        keep[e] = keep_of(tf_bits32(kd0, kd1, 0u, rowb + (uint32_t)(c0 + e)));

    const bool interior = (blockIdx.x != 0) & (blockIdx.x != gridDim.x - 1) &
                          (blockIdx.y != 0) & (blockIdx.y != gridDim.y - 1);

    float res[4];
    if (interior) {
        // all guards true: r in [8,2039], c in [32,2011]
        const float4 ctr = *reinterpret_cast<const float4*>(&g_dnT[rowb + c0]);
        const float* up_row = &g_dnT[rowb - PM];
        const float* dn_row = &g_dnT[rowb + PM];
        const float4 u4 = *reinterpret_cast<const float4*>(up_row + c0);
        const float4 d4 = *reinterpret_cast<const float4*>(dn_row + c0);
        float up[6], dw[6];
        up[1] = u4.x; up[2] = u4.y; up[3] = u4.z; up[4] = u4.w;
        dw[1] = d4.x; dw[2] = d4.y; dw[3] = d4.z; dw[4] = d4.w;
        up[0] = up_row[c0 - 1]; up[5] = up_row[c0 + 4];
        dw[0] = dn_row[c0 - 1]; dw[5] = dn_row[c0 + 4];

        const float cx[4] = {ctr.x, ctr.y, ctr.z, ctr.w};
#pragma unroll
        for (int e = 0; e < 4; ++e) {
            const float x = cx[e];
            const float m = fminf(fminf(fabsf(up[e] - x), fabsf(up[e + 2] - x)),
                                  fminf(fabsf(dw[e] - x), fabsf(dw[e + 2] - x)));
            res[e] = ((m <= thr) && keep[e]) ? 1.0f : 0.0f;
        }
    } else {
        // general guarded path (R7-proven)
        const bool rm = (r >= 1), rp = (r <= PM - 2);
        const float4 ctr = *reinterpret_cast<const float4*>(&g_dnT[rowb + c0]);
        const float* up_row = &g_dnT[(uint32_t)(rm ? r - 1 : r) << 11];
        const float* dn_row = &g_dnT[(uint32_t)(rp ? r + 1 : r) << 11];
        const int cl = (c0 > 0) ? c0 - 1 : 0;
        const int cr = (c0 + 4 < PN) ? c0 + 4 : PN - 1;

        float up[6], dw[6];
        const float4 u4 = *reinterpret_cast<const float4*>(up_row + c0);
        const float4 d4 = *reinterpret_cast<const float4*>(dn_row + c0);
        up[1] = u4.x; up[2] = u4.y; up[3] = u4.z; up[4] = u4.w;
        dw[1] = d4.x; dw[2] = d4.y; dw[3] = d4.z; dw[4] = d4.w;
        up[0] = up_row[cl]; up[5] = up_row[cr];
        dw[0] = dn_row[cl]; dw[5] = dn_row[cr];

        const float cx[4] = {ctr.x, ctr.y, ctr.z, ctr.w};
#pragma unroll
        for (int e = 0; e < 4; ++e) {
            const int c = c0 + e;
            const bool cm = (c >= 1), cp = (c <= PN - 2);
            const float x = cx[e];
            bool adj = false;
            adj |= (cm && rm)             && (fabsf(up[e]     - x) <= thr);
            adj |= (cm && cp && rm && rp) && (fabsf(up[e + 2] - x) <= thr);
            adj |= (cm && rp)             && (fabsf(dw[e]     - x) <= thr);
            adj |= (cp && rp)             && (fabsf(dw[e + 2] - x) <= thr);
            res[e] = (adj && keep[e]) ? 1.0f : 0.0f;
        }
    }

    *reinterpret_cast<float4*>(&out[rowb + c0]) =
        make_float4(res[0], res[1], res[2], res[3]);
}

extern "C" void kernel_launch(void* const* d_in, const int* in_sizes, int n_in,
                              void* d_out, int out_size) {
    (void)in_sizes; (void)n_in; (void)out_size;
    const float* dc = (const float*)d_in[0];
    float* out = (float*)d_out;

    uint32_t kn0, kn1, kd0, kd1;
    tf2x32(0u, 1u, 0u, 0u, kn0, kn1);   // k_noise
    tf2x32(0u, 1u, 0u, 1u, kd0, kd1);   // k_drop

    void* pmin = nullptr; void* pmax = nullptr;
    cudaGetSymbolAddress(&pmin, g_min_u);
    cudaGetSymbolAddress(&pmax, g_max_u);
    cudaMemsetAsync(pmin, 0xFF, 4);
    cudaMemsetAsync(pmax, 0x00, 4);

    pool_noise_kernel<<<dim3(64, 64), dim3(32, 8)>>>(dc, kn0, kn1);
    graph_kernel<<<dim3(16, 256), dim3(32, 8)>>>(out, kd0, kd1);
}

// round 10
// speedup vs baseline: 1.3977x; 1.2721x over previous
#include <cuda_runtime.h>
#include <stdint.h>

// ---------------------------------------------------------------------------
// ExtractGraph: maxpool2x2 -> +uniform noise -> diagonal-stencil adjacency
// (transposed) -> bernoulli(0.5) dropout. Output float32.
// RNG = JAX threefry2x32, partitionable scheme:
//   split(key)[i]      = both output words of threefry(key, (0, i))
//   random_bits(32)[t] = o0 ^ o1 of threefry(key, (hi(t), lo(t)))
// R10: graph computes the stencil FIRST and runs the dropout cipher only for
// adj-true elements (~1.5%) under a divergent branch -> ~4x less cipher work.
// Pool uses float4 loads (2 pool elems/thread) to cut LDG issue in half.
// ---------------------------------------------------------------------------

#define PM 2048
#define PN 2048

static __device__ float    g_dnT[(size_t)PM * PN];   // d_noised TRANSPOSED: g_dnT[j][i]
static __device__ unsigned g_min_u;
static __device__ unsigned g_max_u;

__host__ __device__ __forceinline__ uint32_t rotl32(uint32_t x, int d) {
    return (x << d) | (x >> (32 - d));
}

// Threefry-2x32, 20 rounds, exactly as in jax/_src/prng.py.
__host__ __device__ __forceinline__ void tf2x32(uint32_t k0, uint32_t k1,
                                                uint32_t c0, uint32_t c1,
                                                uint32_t& o0, uint32_t& o1) {
    uint32_t ks2 = k0 ^ k1 ^ 0x1BD11BDAu;
    uint32_t x0 = c0 + k0;
    uint32_t x1 = c1 + k1;
#define TFR(R) { x0 += x1; x1 = rotl32(x1, R); x1 ^= x0; }
    TFR(13) TFR(15) TFR(26) TFR(6)
    x0 += k1;  x1 += ks2 + 1u;
    TFR(17) TFR(29) TFR(16) TFR(24)
    x0 += ks2; x1 += k0 + 2u;
    TFR(13) TFR(15) TFR(26) TFR(6)
    x0 += k0;  x1 += k1 + 3u;
    TFR(17) TFR(29) TFR(16) TFR(24)
    x0 += k1;  x1 += ks2 + 4u;
    TFR(13) TFR(15) TFR(26) TFR(6)
    x0 += ks2; x1 += k0 + 5u;
#undef TFR
    o0 = x0; o1 = x1;
}

__device__ __forceinline__ uint32_t tf_bits32(uint32_t k0, uint32_t k1,
                                              uint32_t c0, uint32_t c1) {
    uint32_t o0, o1;
    tf2x32(k0, k1, c0, c1, o0, o1);
    return o0 ^ o1;
}

// JAX uniform(0,1) float32 from 32 random bits.
__device__ __forceinline__ float u01(uint32_t b) {
    return __uint_as_float((b >> 9) | 0x3f800000u) - 1.0f;
}

// Order-preserving float<->uint mapping for atomic min/max (no NaNs in input).
__device__ __forceinline__ unsigned f2sortable(float f) {
    unsigned u = __float_as_uint(f);
    return (u & 0x80000000u) ? ~u : (u | 0x80000000u);
}
__device__ __forceinline__ float sortable2f(unsigned u) {
    unsigned b = (u & 0x80000000u) ? (u ^ 0x80000000u) : ~u;
    return __uint_as_float(b);
}

// Kernel A: maxpool 2x2 + threefry noise. float4 loads -> 2 pool elems per
// thread per row-iter. Block (32,8) covers a 64-col x 32-row pool tile.
// Col-major smem staging -> conflict-free transposed drain to g_dnT.
__global__ void __launch_bounds__(256) pool_noise_kernel(
    const float* __restrict__ dc, uint32_t kn0, uint32_t kn1) {
    __shared__ float s[64][33];          // s[col_local][row_local]
    const int tx = threadIdx.x, ty = threadIdx.y;
    const int j0 = blockIdx.x * 64;      // pool col tile (64 wide)
    const int i0 = blockIdx.y * 32;      // pool row tile
    const int jj = 2 * tx;               // local col pair base

    unsigned lmin = 0xFFFFFFFFu, lmax = 0u;

#pragma unroll
    for (int k = 0; k < 4; ++k) {
        const int i = i0 + ty + 8 * k;
        const float4* row0 = reinterpret_cast<const float4*>(dc + ((uint32_t)(2 * i) << 12));
        const float4* row1 = reinterpret_cast<const float4*>(dc + ((uint32_t)(2 * i + 1) << 12));
        const float4 a = __ldg(&row0[(j0 >> 1) + tx]);
        const float4 b = __ldg(&row1[(j0 >> 1) + tx]);
        const float p0 = fmaxf(fmaxf(a.x, a.y), fmaxf(b.x, b.y));
        const float p1 = fmaxf(fmaxf(a.z, a.w), fmaxf(b.z, b.w));

        const unsigned e0 = f2sortable(p0), e1 = f2sortable(p1);
        lmin = min(lmin, min(e0, e1));
        lmax = max(lmax, max(e0, e1));

        // two independent cipher chains (ILP)
        const uint32_t t0 = ((uint32_t)i << 11) + (uint32_t)(j0 + jj);
        const uint32_t bn0 = tf_bits32(kn0, kn1, 0u, t0);
        const uint32_t bn1 = tf_bits32(kn0, kn1, 0u, t0 + 1u);

        const int l = ty + 8 * k;
        s[jj][l]     = p0 + u01(bn0);
        s[jj + 1][l] = p1 + u01(bn1);
    }
    __syncthreads();

    // drain: thread (tx,ty) writes cols c = ty*8..ty*8+7, rows i0+tx
    // s[c][tx] is conflict-free (row index contiguous per warp).
#pragma unroll
    for (int k = 0; k < 8; ++k) {
        const int c = ty * 8 + k;
        g_dnT[((uint32_t)(j0 + c) << 11) + i0 + tx] = s[c][tx];
    }

    lmin = __reduce_min_sync(0xffffffffu, lmin);
    lmax = __reduce_max_sync(0xffffffffu, lmax);
    __shared__ unsigned rmin[8], rmax[8];
    if (tx == 0) { rmin[ty] = lmin; rmax[ty] = lmax; }
    __syncthreads();
    if (ty == 0 && tx == 0) {
        unsigned m0 = rmin[0], m1 = rmax[0];
#pragma unroll
        for (int w = 1; w < 8; ++w) { m0 = min(m0, rmin[w]); m1 = max(m1, rmax[w]); }
        atomicMin(&g_min_u, m0);
        atomicMax(&g_max_u, m1);
    }
}

// Kernel B: stencil first, dropout cipher ONLY for adj-true elements (rare).
// 4 elements/thread, float4 I/O, interior/rim block specialization.
__global__ void __launch_bounds__(256) graph_kernel(
    float* __restrict__ out, uint32_t kd0, uint32_t kd1) {
    const int c0 = (blockIdx.x * 32 + threadIdx.x) * 4;
    const int r  = blockIdx.y * 8 + threadIdx.y;

    const float thr = (sortable2f(g_max_u) - sortable2f(g_min_u)) * (1.0f / 2048.0f);
    const uint32_t rowb = (uint32_t)r << 11;

    const bool interior = (blockIdx.x != 0) & (blockIdx.x != gridDim.x - 1) &
                          (blockIdx.y != 0) & (blockIdx.y != gridDim.y - 1);

    bool adj[4];
    if (interior) {
        const float4 ctr = *reinterpret_cast<const float4*>(&g_dnT[rowb + c0]);
        const float* up_row = &g_dnT[rowb - PM];
        const float* dn_row = &g_dnT[rowb + PM];
        const float4 u4 = *reinterpret_cast<const float4*>(up_row + c0);
        const float4 d4 = *reinterpret_cast<const float4*>(dn_row + c0);
        float up[6], dw[6];
        up[1] = u4.x; up[2] = u4.y; up[3] = u4.z; up[4] = u4.w;
        dw[1] = d4.x; dw[2] = d4.y; dw[3] = d4.z; dw[4] = d4.w;
        up[0] = up_row[c0 - 1]; up[5] = up_row[c0 + 4];
        dw[0] = dn_row[c0 - 1]; dw[5] = dn_row[c0 + 4];

        const float cx[4] = {ctr.x, ctr.y, ctr.z, ctr.w};
#pragma unroll
        for (int e = 0; e < 4; ++e) {
            const float x = cx[e];
            const float m = fminf(fminf(fabsf(up[e] - x), fabsf(up[e + 2] - x)),
                                  fminf(fabsf(dw[e] - x), fabsf(dw[e + 2] - x)));
            adj[e] = (m <= thr);
        }
    } else {
        const bool rm = (r >= 1), rp = (r <= PM - 2);
        const float4 ctr = *reinterpret_cast<const float4*>(&g_dnT[rowb + c0]);
        const float* up_row = &g_dnT[(uint32_t)(rm ? r - 1 : r) << 11];
        const float* dn_row = &g_dnT[(uint32_t)(rp ? r + 1 : r) << 11];
        const int cl = (c0 > 0) ? c0 - 1 : 0;
        const int cr = (c0 + 4 < PN) ? c0 + 4 : PN - 1;

        float up[6], dw[6];
        const float4 u4 = *reinterpret_cast<const float4*>(up_row + c0);
        const float4 d4 = *reinterpret_cast<const float4*>(dn_row + c0);
        up[1] = u4.x; up[2] = u4.y; up[3] = u4.z; up[4] = u4.w;
        dw[1] = d4.x; dw[2] = d4.y; dw[3] = d4.z; dw[4] = d4.w;
        up[0] = up_row[cl]; up[5] = up_row[cr];
        dw[0] = dn_row[cl]; dw[5] = dn_row[cr];

        const float cx[4] = {ctr.x, ctr.y, ctr.z, ctr.w};
#pragma unroll
        for (int e = 0; e < 4; ++e) {
            const int c = c0 + e;
            const bool cm = (c >= 1), cp = (c <= PN - 2);
            const float x = cx[e];
            bool a = false;
            a |= (cm && rm)             && (fabsf(up[e]     - x) <= thr);
            a |= (cm && cp && rm && rp) && (fabsf(up[e + 2] - x) <= thr);
            a |= (cm && rp)             && (fabsf(dw[e]     - x) <= thr);
            a |= (cp && rp)             && (fabsf(dw[e + 2] - x) <= thr);
            adj[e] = a;
        }
    }

    // dropout cipher only where adj is true (~1.5% of elements). When skipped
    // the output is 0 regardless of the draw, so results stay bit-exact.
    float res[4];
#pragma unroll
    for (int e = 0; e < 4; ++e) {
        float v = 0.0f;
        if (adj[e]) {
            const uint32_t bd = tf_bits32(kd0, kd1, 0u, rowb + (uint32_t)(c0 + e));
            v = (bd & 0x80000000u) ? 0.0f : 1.0f;   // u01(bd) < 0.5 exact
        }
        res[e] = v;
    }

    *reinterpret_cast<float4*>(&out[rowb + c0]) =
        make_float4(res[0], res[1], res[2], res[3]);
}

extern "C" void kernel_launch(void* const* d_in, const int* in_sizes, int n_in,
                              void* d_out, int out_size) {
    (void)in_sizes; (void)n_in; (void)out_size;
    const float* dc = (const float*)d_in[0];
    float* out = (float*)d_out;

    uint32_t kn0, kn1, kd0, kd1;
    tf2x32(0u, 1u, 0u, 0u, kn0, kn1);   // k_noise
    tf2x32(0u, 1u, 0u, 1u, kd0, kd1);   // k_drop

    void* pmin = nullptr; void* pmax = nullptr;
    cudaGetSymbolAddress(&pmin, g_min_u);
    cudaGetSymbolAddress(&pmax, g_max_u);
    cudaMemsetAsync(pmin, 0xFF, 4);
    cudaMemsetAsync(pmax, 0x00, 4);

    pool_noise_kernel<<<dim3(32, 64), dim3(32, 8)>>>(dc, kn0, kn1);
    graph_kernel<<<dim3(16, 256), dim3(32, 8)>>>(out, kd0, kd1);
}